// round 8
// baseline (speedup 1.0000x reference)
#include <cuda_runtime.h>

#define BB 4
#define CC 64
#define TN 64
#define NN 4096
#define GRID 256

typedef unsigned long long ull;

// scratch (allocation-free rule: __device__ globals, zero-initialized)
__device__ float g_a[BB * NN];
__device__ float g_d[BB * NN];
__device__ float g_u[BB * CC];
__device__ float g_v[BB * CC];
__device__ float g_W0t[CC * CC];     // [c][o]
__device__ float g_W1t[CC * CC];     // [c][o]
__device__ float g_scale[CC];
__device__ float g_shift[CC];
__device__ unsigned g_bar;           // monotonic barrier counter

// ---- f32x2 packed helpers ---------------------------------------------------
__device__ __forceinline__ ull pack2(float lo, float hi) {
    ull r; asm("mov.b64 %0, {%1, %2};" : "=l"(r) : "f"(lo), "f"(hi)); return r;
}
__device__ __forceinline__ void unpack2(ull v, float& lo, float& hi) {
    asm("mov.b64 {%0, %1}, %2;" : "=f"(lo), "=f"(hi) : "l"(v));
}
__device__ __forceinline__ ull fma2(ull a, ull b, ull c) {
    ull d; asm("fma.rn.f32x2 %0, %1, %2, %3;" : "=l"(d) : "l"(a), "l"(b), "l"(c)); return d;
}
__device__ __forceinline__ ull mul2(ull a, ull b) {
    ull d; asm("mul.rn.f32x2 %0, %1, %2;" : "=l"(d) : "l"(a), "l"(b)); return d;
}

__device__ __forceinline__ float relutanh(float x) {
    if (x <= 0.f) return 0.f;
    float e = __expf(-2.f * x);
    return (1.f - e) * __frcp_rn(1.f + e);
}

// device-wide barrier: monotonic counter; release fence writer-side,
// acquire-ish fence reader-side after the spin.
__device__ __forceinline__ void grid_barrier(int tid) {
    __threadfence();
    __syncthreads();
    if (tid == 0) {
        unsigned old = atomicAdd(&g_bar, 1u);
        unsigned target = (old & ~(unsigned)(GRID - 1)) + GRID;
        unsigned vcur;
        do { vcur = *(volatile unsigned*)&g_bar; } while ((int)(vcur - target) < 0);
        __threadfence();
    }
    __syncthreads();
}

// -----------------------------------------------------------------------------
// Single fused kernel. grid=256, 256 threads, 48KB dynamic smem.
// Pre-A : all blocks stage x-tile; c==0 blocks (4) compute a,S,d full-N;
//         b==0 blocks transpose conv_w row c; blk 0 folds BN.
// Post-A: stage weights from g_W0t/g_W1t; compute u,v for (b,c) using
//         g_a/g_d (plain loads — written this kernel, NOT __ldg-safe).
// Post-B: p/q, f32x2 GEMM, rank-1 + BN + ReLU epilogue.
// -----------------------------------------------------------------------------
__global__ void __launch_bounds__(256, 2) k_fused(
        const float* __restrict__ x,
        const float* __restrict__ w,
        const float* __restrict__ conv_w,
        const float* __restrict__ conv_b,
        const float* __restrict__ gamma,
        const float* __restrict__ beta,
        const float* __restrict__ mean,
        const float* __restrict__ var,
        float* __restrict__ out) {
    extern __shared__ float sm[];
    float* xs  = sm;                  // [64][64] plain x      16KB
    float* w0s = sm + CC * TN;        // [c][o]                16KB
    float* w1s = w0s + CC * CC;       //                       16KB
    __shared__ float p_s[CC], q_s[CC], u_s[CC], v_s[CC];
    __shared__ float red[8], red2[8];
    __shared__ float S_sh;

    const int tid = threadIdx.x;
    const int blk = blockIdx.x;
    const int b = blk >> 6;
    const int c = blk & 63;
    const int n0 = c * TN;            // phase-2 tile == c

    // ================= Pre-A =================
    {
        const float* xb = x + (size_t)(b * CC) * NN + n0;
        float4* xs4 = (float4*)xs;
        #pragma unroll
        for (int k = 0; k < 4; k++) {
            int i = tid + k * 256;          // 1024 float4 = 64 rows x 16
            int cc2 = i >> 4, j = i & 15;
            xs4[i] = ((const float4*)(xb + cc2 * NN))[j];
        }
    }

    if (c == 0) {
        // a = relu(tanh(w)), S, d for full N  (only 4 blocks do MUFU work)
        const float4* w4 = (const float4*)(w + b * NN);
        float avr[16];
        float s = 0.f;
        #pragma unroll
        for (int k = 0; k < 4; k++) {
            float4 wv = w4[tid + k * 256];
            avr[k*4+0] = relutanh(wv.x);
            avr[k*4+1] = relutanh(wv.y);
            avr[k*4+2] = relutanh(wv.z);
            avr[k*4+3] = relutanh(wv.w);
            s += avr[k*4+0] + avr[k*4+1] + avr[k*4+2] + avr[k*4+3];
        }
        #pragma unroll
        for (int off = 16; off; off >>= 1) s += __shfl_down_sync(0xffffffffu, s, off);
        if ((tid & 31) == 0) red[tid >> 5] = s;
        __syncthreads();
        if (tid == 0) {
            float t = 0.f;
            #pragma unroll
            for (int i = 0; i < 8; i++) t += red[i];
            S_sh = t;
        }
        __syncthreads();
        const float S = S_sh;
        #pragma unroll
        for (int k = 0; k < 4; k++) {
            ((float4*)(g_a + b * NN))[tid + k * 256] =
                make_float4(avr[k*4+0], avr[k*4+1], avr[k*4+2], avr[k*4+3]);
            float4 dv;
            dv.x = rsqrtf(fmaf(avr[k*4+0], S, 1.f));
            dv.y = rsqrtf(fmaf(avr[k*4+1], S, 1.f));
            dv.z = rsqrtf(fmaf(avr[k*4+2], S, 1.f));
            dv.w = rsqrtf(fmaf(avr[k*4+3], S, 1.f));
            ((float4*)(g_d + b * NN))[tid + k * 256] = dv;
        }
    }
    if (b == 0) {
        if (tid < CC) {
            g_W0t[c * CC + tid] = conv_w[tid * 128 + c];
            g_W1t[c * CC + tid] = conv_w[tid * 128 + CC + c];
        }
        if (c == 0 && tid >= 64 && tid < 128) {
            int o = tid - 64;
            float sc = gamma[o] * rsqrtf(var[o] + 1e-5f);
            g_scale[o] = sc;
            g_shift[o] = fmaf(conv_b[o] - mean[o], sc, beta[o]);
        }
    }

    // ================= Barrier A =================
    grid_barrier(tid);

    // ================= Post-A =================
    // stage weights (linear copy, coalesced)
    {
        float4* w0s4 = (float4*)w0s;
        float4* w1s4 = (float4*)w1s;
        const float4* gw0 = (const float4*)g_W0t;
        const float4* gw1 = (const float4*)g_W1t;
        #pragma unroll
        for (int k = 0; k < 4; k++) {
            int i = tid + k * 256;          // 1024 float4 each
            w0s4[i] = gw0[i];
            w1s4[i] = gw1[i];
        }
    }
    // u = sum_n x[c,n] a[n] ; v = sum_n x[c,n] a[n] d[n]  (PLAIN loads of a,d)
    {
        const float4* x4 = (const float4*)(x + (size_t)(b * CC + c) * NN);
        const float4* a4 = (const float4*)(g_a + b * NN);
        const float4* d4 = (const float4*)(g_d + b * NN);
        float su = 0.f, sv = 0.f;
        #pragma unroll
        for (int k = 0; k < 4; k++) {
            int i = tid + k * 256;
            float4 xv = x4[i];
            float4 av = a4[i];
            float4 dv = d4[i];
            float t0 = xv.x * av.x, t1 = xv.y * av.y;
            float t2 = xv.z * av.z, t3 = xv.w * av.w;
            su += t0 + t1 + t2 + t3;
            sv += t0 * dv.x + t1 * dv.y + t2 * dv.z + t3 * dv.w;
        }
        #pragma unroll
        for (int off = 16; off; off >>= 1) {
            su += __shfl_down_sync(0xffffffffu, su, off);
            sv += __shfl_down_sync(0xffffffffu, sv, off);
        }
        if ((tid & 31) == 0) { red[tid >> 5] = su; red2[tid >> 5] = sv; }
        __syncthreads();
        if (tid == 0) {
            float tu = 0.f, tv = 0.f;
            #pragma unroll
            for (int i = 0; i < 8; i++) { tu += red[i]; tv += red2[i]; }
            g_u[b * CC + c] = tu;
            g_v[b * CC + c] = tv;
        }
    }

    // ================= Barrier B =================
    grid_barrier(tid);

    // ================= Phase 2 =================
    if (tid < CC) {
        u_s[tid] = g_u[b * CC + tid];
        v_s[tid] = g_v[b * CC + tid];
    }
    __syncthreads();

    // p[o] = sum_c W0t[c][o] u[c] ; q[o] = sum_c W1t[c][o] v[c]
    if (tid < 128) {
        const int o = tid & 63;
        const bool isq = tid >= 64;
        const float* W = isq ? w1s : w0s;
        const float* uv = isq ? v_s : u_s;
        float s = 0.f;
        #pragma unroll 8
        for (int cc2 = 0; cc2 < CC; cc2++) s = fmaf(W[cc2 * CC + o], uv[cc2], s);
        (isq ? q_s : p_s)[o] = s;
    }
    __syncthreads();

    const int warp = tid >> 5, lane = tid & 31;
    const int ow = warp << 3;           // 8 o per warp (4 o-pairs)
    const int ng = n0 + 2 * lane;       // 2 n per lane

    const float2 a2 = *(const float2*)(g_a + b * NN + ng);
    const float2 d2 = *(const float2*)(g_d + b * NN + ng);
    const ull ddp0 = pack2(d2.x * d2.x, d2.x * d2.x);
    const ull ddp1 = pack2(d2.y * d2.y, d2.y * d2.y);

    ull acc[4][2];                      // [o-pair][n]
    #pragma unroll
    for (int i = 0; i < 4; i++) { acc[i][0] = 0ull; acc[i][1] = 0ull; }

    const float* xp  = xs  + 2 * lane;
    const float* w0p = w0s + ow;
    const float* w1p = w1s + ow;

    #pragma unroll 8
    for (int k = 0; k < CC; k++) {
        float2 xv = *(const float2*)(xp + k * TN);
        ull xd0 = pack2(xv.x, xv.x);
        ull xd1 = pack2(xv.y, xv.y);
        ull xq0 = mul2(xd0, ddp0);
        ull xq1 = mul2(xd1, ddp1);
        ulonglong2 wa0 = *(const ulonglong2*)(w0p + k * CC);
        ulonglong2 wb0 = *(const ulonglong2*)(w0p + k * CC + 4);
        ulonglong2 wa1 = *(const ulonglong2*)(w1p + k * CC);
        ulonglong2 wb1 = *(const ulonglong2*)(w1p + k * CC + 4);
        acc[0][0] = fma2(wa0.x, xd0, acc[0][0]);
        acc[0][1] = fma2(wa0.x, xd1, acc[0][1]);
        acc[1][0] = fma2(wa0.y, xd0, acc[1][0]);
        acc[1][1] = fma2(wa0.y, xd1, acc[1][1]);
        acc[2][0] = fma2(wb0.x, xd0, acc[2][0]);
        acc[2][1] = fma2(wb0.x, xd1, acc[2][1]);
        acc[3][0] = fma2(wb0.y, xd0, acc[3][0]);
        acc[3][1] = fma2(wb0.y, xd1, acc[3][1]);
        acc[0][0] = fma2(wa1.x, xq0, acc[0][0]);
        acc[0][1] = fma2(wa1.x, xq1, acc[0][1]);
        acc[1][0] = fma2(wa1.y, xq0, acc[1][0]);
        acc[1][1] = fma2(wa1.y, xq1, acc[1][1]);
        acc[2][0] = fma2(wb1.x, xq0, acc[2][0]);
        acc[2][1] = fma2(wb1.x, xq1, acc[2][1]);
        acc[3][0] = fma2(wb1.y, xq0, acc[3][0]);
        acc[3][1] = fma2(wb1.y, xq1, acc[3][1]);
    }

    // epilogue: y = acc + p*a_n + q*(d*a)_n ; BN ; ReLU
    const ull ap0  = pack2(a2.x, a2.x);
    const ull ap1  = pack2(a2.y, a2.y);
    const ull dap0 = pack2(d2.x * a2.x, d2.x * a2.x);
    const ull dap1 = pack2(d2.y * a2.y, d2.y * a2.y);

    float* ob = out + (size_t)(b * CC) * NN + ng;
    #pragma unroll
    for (int j = 0; j < 4; j++) {
        const int o0 = ow + 2 * j;
        ull pp = *(const ull*)(p_s + o0);
        ull qq = *(const ull*)(q_s + o0);
        ull sc = *(const ull*)(g_scale + o0);
        ull sh = *(const ull*)(g_shift + o0);
        ull y0 = fma2(pp, ap0, acc[j][0]);
        y0 = fma2(qq, dap0, y0);
        y0 = fma2(y0, sc, sh);
        ull y1 = fma2(pp, ap1, acc[j][1]);
        y1 = fma2(qq, dap1, y1);
        y1 = fma2(y1, sc, sh);
        float f00, f10, f01, f11;
        unpack2(y0, f00, f10);
        unpack2(y1, f01, f11);
        f00 = fmaxf(f00, 0.f); f01 = fmaxf(f01, 0.f);
        f10 = fmaxf(f10, 0.f); f11 = fmaxf(f11, 0.f);
        *(float2*)(ob + (size_t)o0 * NN)       = make_float2(f00, f01);
        *(float2*)(ob + (size_t)(o0 + 1) * NN) = make_float2(f10, f11);
    }
}

// -----------------------------------------------------------------------------
extern "C" void kernel_launch(void* const* d_in, const int* in_sizes, int n_in,
                              void* d_out, int out_size) {
    const float* x      = (const float*)d_in[0];
    const float* w      = (const float*)d_in[1];
    const float* conv_w = (const float*)d_in[2];
    const float* conv_b = (const float*)d_in[3];
    const float* gamma  = (const float*)d_in[4];
    const float* beta   = (const float*)d_in[5];
    const float* mean   = (const float*)d_in[6];
    const float* var    = (const float*)d_in[7];
    float* out = (float*)d_out;

    const int smem = (CC * TN + 2 * CC * CC) * sizeof(float);  // 48 KB
    cudaFuncSetAttribute(k_fused, cudaFuncAttributeMaxDynamicSharedMemorySize, smem);

    k_fused<<<GRID, 256, smem>>>(x, w, conv_w, conv_b, gamma, beta, mean, var, out);
}